// round 2
// baseline (speedup 1.0000x reference)
#include <cuda_runtime.h>
#include <cuda_bf16.h>

#define NPTS 512
#define HDIM 128
#define TP   128          // pairs per block tile
#define KC   16           // k-chunk for W2 staging
#define NC   (HDIM / KC)  // 8 chunks
#define THREADS 256
#define NPAIRS 130816     // N*(N-1)/2
#define NTILES 1022       // NPAIRS / TP (exact)

struct Smem {
    float h1s[HDIM][TP];   // h1 stored k-major: h1s[k][pair]
    float w2s[KC][HDIM];   // W2 chunk [k][d]
    float feats[TP][4];    // r, 1/r, 1/r^2, pad
    float w1s[3][HDIM];
    float b1s[HDIM];
    float b2s[HDIM];
    float w3s[HDIM];
    float red[32];
};

__device__ __forceinline__ float silu(float h) {
    return h / (1.0f + __expf(-h));
}

__global__ void init_out_kernel(float* out, const float* b3) {
    int b = threadIdx.x;
    if (b < 8) out[b] = (float)NPAIRS * b3[0];
}

__global__ __launch_bounds__(THREADS)
void discovery_kernel(const float* __restrict__ pos,
                      const float* __restrict__ W1,
                      const float* __restrict__ b1,
                      const float* __restrict__ W2,
                      const float* __restrict__ b2,
                      const float* __restrict__ W3,
                      float* __restrict__ out) {
    extern __shared__ char smem_raw[];
    Smem* s = reinterpret_cast<Smem*>(smem_raw);

    const int t    = threadIdx.x;
    const int bat  = blockIdx.y;
    const int tile = blockIdx.x;

    // ---- load weights into shared ----
    for (int idx = t; idx < 3 * HDIM; idx += THREADS)
        s->w1s[idx / HDIM][idx % HDIM] = W1[idx];
    for (int idx = t; idx < HDIM; idx += THREADS) {
        s->b1s[idx] = b1[idx];
        s->b2s[idx] = b2[idx];
        s->w3s[idx] = W3[idx];
    }

    // ---- Stage A: pair indices + features (threads 0..127) ----
    if (t < TP) {
        int p = tile * TP + t;  // global unordered pair index, < NPAIRS
        // row i: S(i) = i*(2N-1-i)/2 <= p < S(i+1)
        double tn = 2.0 * NPTS - 1.0;
        int i = (int)floor((tn - sqrt(tn * tn - 8.0 * (double)p)) * 0.5);
        if (i < 0) i = 0;
        while ((long)(i + 1) * (2 * NPTS - 1 - (i + 1)) / 2 <= p) i++;
        while ((long)i * (2 * NPTS - 1 - i) / 2 > p) i--;
        long s0 = (long)i * (2 * NPTS - 1 - i) / 2;
        int j = i + 1 + (int)(p - s0);

        const float* pb = pos + (size_t)bat * NPTS * 3;
        float dx = pb[i * 3 + 0] - pb[j * 3 + 0];
        float dy = pb[i * 3 + 1] - pb[j * 3 + 1];
        float dz = pb[i * 3 + 2] - pb[j * 3 + 2];
        float r = sqrtf(dx * dx + dy * dy + dz * dz);
        r = fmaxf(r, 0.05f);
        float ri = 1.0f / r;
        s->feats[t][0] = r;
        s->feats[t][1] = ri;
        s->feats[t][2] = ri * ri;
    }
    __syncthreads();

    // ---- Stage B: h1 = silu(feats @ W1 + b1), stored k-major ----
    {
        int pp   = t >> 1;
        int base = (t & 1) * 64;
        float f0 = s->feats[pp][0];
        float f1 = s->feats[pp][1];
        float f2 = s->feats[pp][2];
        #pragma unroll 8
        for (int d = base; d < base + 64; ++d) {
            float h = fmaf(f0, s->w1s[0][d],
                      fmaf(f1, s->w1s[1][d],
                      fmaf(f2, s->w1s[2][d], s->b1s[d])));
            s->h1s[d][pp] = silu(h);
        }
    }
    __syncthreads();

    // ---- Stage C: GEMM  h2raw[p][d] = sum_k h1[p][k] * W2[k][d] ----
    const int tx = t & 15;        // d group
    const int ty = t >> 4;        // p group
    const int d0 = tx * 8;
    const int p0 = ty * 8;

    float acc[8][8];
    #pragma unroll
    for (int a = 0; a < 8; ++a)
        #pragma unroll
        for (int bb = 0; bb < 8; ++bb) acc[a][bb] = 0.0f;

    // prefetch indexing: each thread owns 8 consecutive floats of a 2048-float chunk
    const int pidx = t * 8;
    const int pkk  = pidx >> 7;     // row within chunk
    const int pdd  = pidx & 127;    // col
    float4 pre0 = *(const float4*)(W2 + pkk * HDIM + pdd);
    float4 pre1 = *(const float4*)(W2 + pkk * HDIM + pdd + 4);

    for (int c = 0; c < NC; ++c) {
        *(float4*)&s->w2s[pkk][pdd]     = pre0;
        *(float4*)&s->w2s[pkk][pdd + 4] = pre1;
        __syncthreads();
        if (c + 1 < NC) {
            const float* src = W2 + ((c + 1) * KC + pkk) * HDIM + pdd;
            pre0 = *(const float4*)src;
            pre1 = *(const float4*)(src + 4);
        }
        #pragma unroll
        for (int kk = 0; kk < KC; ++kk) {
            const float4 a0 = *(const float4*)&s->h1s[c * KC + kk][p0];
            const float4 a1 = *(const float4*)&s->h1s[c * KC + kk][p0 + 4];
            const float4 w0 = *(const float4*)&s->w2s[kk][d0];
            const float4 w1v = *(const float4*)&s->w2s[kk][d0 + 4];
            float av[8] = {a0.x, a0.y, a0.z, a0.w, a1.x, a1.y, a1.z, a1.w};
            float wv[8] = {w0.x, w0.y, w0.z, w0.w, w1v.x, w1v.y, w1v.z, w1v.w};
            #pragma unroll
            for (int pi = 0; pi < 8; ++pi)
                #pragma unroll
                for (int di = 0; di < 8; ++di)
                    acc[pi][di] = fmaf(av[pi], wv[di], acc[pi][di]);
        }
        __syncthreads();
    }

    // ---- Stage D: epilogue  sum_p sum_d silu(acc + b2[d]) * W3[d] ----
    float sum = 0.0f;
    #pragma unroll
    for (int di = 0; di < 8; ++di) {
        float bv = s->b2s[d0 + di];
        float wv = s->w3s[d0 + di];
        #pragma unroll
        for (int pi = 0; pi < 8; ++pi) {
            float h = acc[pi][di] + bv;
            sum = fmaf(silu(h), wv, sum);
        }
    }

    // block reduction
    #pragma unroll
    for (int off = 16; off > 0; off >>= 1)
        sum += __shfl_xor_sync(0xFFFFFFFFu, sum, off);
    if ((t & 31) == 0) s->red[t >> 5] = sum;
    __syncthreads();
    if (t == 0) {
        float tot = 0.0f;
        #pragma unroll
        for (int w = 0; w < THREADS / 32; ++w) tot += s->red[w];
        atomicAdd(&out[bat], tot);
    }
}

extern "C" void kernel_launch(void* const* d_in, const int* in_sizes, int n_in,
                              void* d_out, int out_size) {
    const float* pos = (const float*)d_in[0];
    const float* W1  = (const float*)d_in[1];
    const float* b1  = (const float*)d_in[2];
    const float* W2  = (const float*)d_in[3];
    const float* b2  = (const float*)d_in[4];
    const float* W3  = (const float*)d_in[5];
    const float* b3  = (const float*)d_in[6];
    float* out = (float*)d_out;

    cudaFuncSetAttribute(discovery_kernel,
                         cudaFuncAttributeMaxDynamicSharedMemorySize,
                         (int)sizeof(Smem));

    init_out_kernel<<<1, 8>>>(out, b3);
    dim3 grid(NTILES, 8);
    discovery_kernel<<<grid, THREADS, sizeof(Smem)>>>(pos, W1, b1, W2, b2, W3, out);
}

// round 5
// speedup vs baseline: 2.2574x; 2.2574x over previous
#include <cuda_runtime.h>
#include <cuda_bf16.h>
#include <cstdint>

#define NPTS 512
#define HDIM 128
#define TP 128
#define NPAIRS 130816
#define NTILES 1022
#define NBATCH 8
#define THREADS 256
#define BSTRIDE 136   // bf16 elements per B row (padded: 272B, conflict-free ldmatrix)

struct Smem {
    __nv_bfloat16 bhi[HDIM * BSTRIDE];   // W2^T hi  [d][k]
    __nv_bfloat16 blo[HDIM * BSTRIDE];   // W2^T lo
    float w1s[3 * HDIM];
    float b1s[HDIM];
    float b2s[HDIM];
    float w3s[HDIM];
    float red[NBATCH][8];
};

// pre-built transposed + split W2 images
__device__ __align__(16) __nv_bfloat16 g_bhi[HDIM * BSTRIDE];
__device__ __align__(16) __nv_bfloat16 g_blo[HDIM * BSTRIDE];

// ---------------- helpers ----------------
__device__ __forceinline__ uint32_t smem_u32(const void* p) {
    uint32_t a;
    asm("{ .reg .u64 t; cvta.to.shared.u64 t, %1; cvt.u32.u64 %0, t; }" : "=r"(a) : "l"(p));
    return a;
}

__device__ __forceinline__ void ldsm_x4(uint32_t& r0, uint32_t& r1, uint32_t& r2, uint32_t& r3,
                                        uint32_t addr) {
    asm volatile("ldmatrix.sync.aligned.m8n8.x4.shared.b16 {%0,%1,%2,%3}, [%4];"
                 : "=r"(r0), "=r"(r1), "=r"(r2), "=r"(r3) : "r"(addr));
}

__device__ __forceinline__ void mma_bf16(float* c, const uint32_t* a, const uint32_t b0,
                                         const uint32_t b1) {
    asm volatile(
        "mma.sync.aligned.m16n8k16.row.col.f32.bf16.bf16.f32 "
        "{%0,%1,%2,%3}, {%4,%5,%6,%7}, {%8,%9}, {%0,%1,%2,%3};"
        : "+f"(c[0]), "+f"(c[1]), "+f"(c[2]), "+f"(c[3])
        : "r"(a[0]), "r"(a[1]), "r"(a[2]), "r"(a[3]), "r"(b0), "r"(b1));
}

// pack (lo, hi) floats into bf16x2: d[15:0]=lo, d[31:16]=hi
__device__ __forceinline__ uint32_t pack_bf16(float lo, float hi) {
    uint32_t r;
    asm("cvt.rn.bf16x2.f32 %0, %1, %2;" : "=r"(r) : "f"(hi), "f"(lo));
    return r;
}

// silu with 1 MUFU (EX2) + FFMA-only Newton reciprocal
__device__ __forceinline__ float silu_fast(float z) {
    float t = __expf(-fabsf(z));            // (0, 1]
    float x = 1.0f + t;                      // (1, 2]
    float r = __uint_as_float(0x7EF311C3u - __float_as_uint(x));
    r = r * (2.0f - x * r);
    r = r * (2.0f - x * r);                  // 1/x to ~1e-5
    float sig = (z >= 0.0f) ? r : t * r;
    return z * sig;
}

// ---------------- kernels ----------------
__global__ void init_out_kernel(float* out, const float* b3) {
    int b = threadIdx.x;
    if (b < NBATCH) out[b] = (float)NPAIRS * b3[0];
}

__global__ void prep_kernel(const float* __restrict__ W2) {
    int idx = blockIdx.x * blockDim.x + threadIdx.x;
    if (idx >= HDIM * HDIM) return;
    int d = idx & 127;
    int k = idx >> 7;
    float v = W2[idx];                       // W2[k][d]
    __nv_bfloat16 hi = __float2bfloat16(v);
    float lo = v - __bfloat162float(hi);
    g_bhi[d * BSTRIDE + k] = hi;
    g_blo[d * BSTRIDE + k] = __float2bfloat16(lo);
}

__global__ __launch_bounds__(THREADS)
void discovery_hmma(const float* __restrict__ pos,
                    const float* __restrict__ W1,
                    const float* __restrict__ b1,
                    const float* __restrict__ b2,
                    const float* __restrict__ W3,
                    float* __restrict__ out) {
    extern __shared__ char smem_raw[];
    Smem* s = reinterpret_cast<Smem*>(smem_raw);

    const int t = threadIdx.x;
    const int w = t >> 5;
    const int lane = t & 31;
    const int tile = blockIdx.x;

    // ---- stage weights (once) ----
    {
        const uint4* shi = (const uint4*)g_bhi;
        const uint4* slo = (const uint4*)g_blo;
        uint4* dhi = (uint4*)s->bhi;
        uint4* dlo = (uint4*)s->blo;
        for (int i = t; i < (HDIM * BSTRIDE * 2) / 16; i += THREADS) {
            dhi[i] = shi[i];
            dlo[i] = slo[i];
        }
    }
    for (int i = t; i < 3 * HDIM; i += THREADS) s->w1s[i] = W1[i];
    if (t < HDIM) {
        s->b1s[t] = b1[t];
        s->b2s[t] = b2[t];
        s->w3s[t] = W3[t];
    }

    // ---- pair decode: 4 pair-rows per thread ----
    // warp m-block = (w&3)*32; thread rows = lane/4 + {0,8,16,24}
    int ip[4], jp[4];
    {
        const int mrow = (w & 3) * 32 + (lane >> 2);
        #pragma unroll
        for (int q = 0; q < 4; ++q) {
            int p = tile * TP + mrow + q * 8;
            double tn = 2.0 * NPTS - 1.0;
            int i = (int)floor((tn - sqrt(tn * tn - 8.0 * (double)p)) * 0.5);
            if (i < 0) i = 0;
            while ((long)(i + 1) * (2 * NPTS - 1 - (i + 1)) / 2 <= p) i++;
            while ((long)i * (2 * NPTS - 1 - i) / 2 > p) i--;
            long s0 = (long)i * (2 * NPTS - 1 - i) / 2;
            ip[q] = i;
            jp[q] = i + 1 + (int)(p - s0);
        }
    }
    __syncthreads();   // the only block-wide sync before the final reduction

    const uint32_t bhi_base = smem_u32(s->bhi);
    const uint32_t blo_base = smem_u32(s->blo);
    // ldmatrix per-lane offset: groups of 8 lanes -> (row, k) corners
    const int rowoff = (lane & 7) + ((lane >> 4) << 3);
    const int kadd   = ((lane >> 3) & 1) << 3;
    const uint32_t laneB = (uint32_t)(rowoff * BSTRIDE + kadd) * 2u;
    const int nb = (w >> 2) * 64;   // warp n-block

    for (int b = 0; b < NBATCH; ++b) {
        // ---- features for this thread's 4 pairs ----
        float f0[4], f1[4], f2[4];
        {
            const float* pb = pos + (size_t)b * NPTS * 3;
            #pragma unroll
            for (int q = 0; q < 4; ++q) {
                int i = ip[q], j = jp[q];
                float dx = pb[i * 3 + 0] - pb[j * 3 + 0];
                float dy = pb[i * 3 + 1] - pb[j * 3 + 1];
                float dz = pb[i * 3 + 2] - pb[j * 3 + 2];
                float r = sqrtf(dx * dx + dy * dy + dz * dz);
                r = fmaxf(r, 0.05f);
                float ri = 1.0f / r;
                f0[q] = r; f1[q] = ri; f2[q] = ri * ri;
            }
        }

        float acc[2][8][4];
        #pragma unroll
        for (int mt = 0; mt < 2; ++mt)
            #pragma unroll
            for (int nt = 0; nt < 8; ++nt)
                #pragma unroll
                for (int e = 0; e < 4; ++e) acc[mt][nt][e] = 0.0f;

        // ---- mainloop over 8 k-steps (no syncs; A built in registers) ----
        #pragma unroll
        for (int ks = 0; ks < 8; ++ks) {
            const int kb = ks * 16 + (lane & 3) * 2;
            // w1 coefficients for this thread's 4 k's: kb, kb+1, kb+8, kb+9
            float wa[4], wb[4], wc[4], bbv[4];
            #pragma unroll
            for (int u = 0; u < 4; ++u) {
                int k = kb + (u >> 1) * 8 + (u & 1);
                wa[u] = s->w1s[k];
                wb[u] = s->w1s[128 + k];
                wc[u] = s->w1s[256 + k];
                bbv[u] = s->b1s[k];
            }
            // A fragments: afr[mt] = {a0,a1,a2,a3}
            uint32_t afr[2][4];
            #pragma unroll
            for (int mt = 0; mt < 2; ++mt) {
                #pragma unroll
                for (int h = 0; h < 2; ++h) {
                    int q = mt * 2 + h;
                    float z0 = fmaf(f2[q], wc[0], fmaf(f1[q], wb[0], fmaf(f0[q], wa[0], bbv[0])));
                    float z1 = fmaf(f2[q], wc[1], fmaf(f1[q], wb[1], fmaf(f0[q], wa[1], bbv[1])));
                    float z2 = fmaf(f2[q], wc[2], fmaf(f1[q], wb[2], fmaf(f0[q], wa[2], bbv[2])));
                    float z3 = fmaf(f2[q], wc[3], fmaf(f1[q], wb[3], fmaf(f0[q], wa[3], bbv[3])));
                    afr[mt][h]     = pack_bf16(silu_fast(z0), silu_fast(z1)); // k, k+1
                    afr[mt][h + 2] = pack_bf16(silu_fast(z2), silu_fast(z3)); // k+8, k+9
                }
            }
            // B fragments via ldmatrix (hi and lo)
            uint32_t bh[8][2], bl[8][2];
            #pragma unroll
            for (int pr = 0; pr < 4; ++pr) {
                uint32_t off = (uint32_t)((nb + pr * 16) * BSTRIDE + ks * 16) * 2u + laneB;
                ldsm_x4(bh[pr * 2][0], bh[pr * 2][1], bh[pr * 2 + 1][0], bh[pr * 2 + 1][1],
                        bhi_base + off);
                ldsm_x4(bl[pr * 2][0], bl[pr * 2][1], bl[pr * 2 + 1][0], bl[pr * 2 + 1][1],
                        blo_base + off);
            }
            // MMAs: 2 chains
            #pragma unroll
            for (int mt = 0; mt < 2; ++mt)
                #pragma unroll
                for (int nt = 0; nt < 8; ++nt) {
                    mma_bf16(acc[mt][nt], afr[mt], bh[nt][0], bh[nt][1]);
                    mma_bf16(acc[mt][nt], afr[mt], bl[nt][0], bl[nt][1]);
                }
        }

        // ---- epilogue straight from accumulator registers ----
        float sum = 0.0f;
        #pragma unroll
        for (int nt = 0; nt < 8; ++nt) {
            int col = nb + nt * 8 + (lane & 3) * 2;
            float b2a = s->b2s[col], b2b = s->b2s[col + 1];
            float w3a = s->w3s[col], w3b = s->w3s[col + 1];
            #pragma unroll
            for (int mt = 0; mt < 2; ++mt) {
                sum = fmaf(silu_fast(acc[mt][nt][0] + b2a), w3a, sum);
                sum = fmaf(silu_fast(acc[mt][nt][1] + b2b), w3b, sum);
                sum = fmaf(silu_fast(acc[mt][nt][2] + b2a), w3a, sum);
                sum = fmaf(silu_fast(acc[mt][nt][3] + b2b), w3b, sum);
            }
        }
        #pragma unroll
        for (int off = 16; off > 0; off >>= 1)
            sum += __shfl_xor_sync(0xFFFFFFFFu, sum, off);
        if (lane == 0) s->red[b][w] = sum;
    }

    __syncthreads();
    if (w == 0 && lane < NBATCH) {
        float tot = 0.0f;
        #pragma unroll
        for (int wi = 0; wi < 8; ++wi) tot += s->red[lane][wi];
        atomicAdd(&out[lane], tot);
    }
}

extern "C" void kernel_launch(void* const* d_in, const int* in_sizes, int n_in,
                              void* d_out, int out_size) {
    const float* pos = (const float*)d_in[0];
    const float* W1  = (const float*)d_in[1];
    const float* b1  = (const float*)d_in[2];
    const float* W2  = (const float*)d_in[3];
    const float* b2  = (const float*)d_in[4];
    const float* W3  = (const float*)d_in[5];
    const float* b3  = (const float*)d_in[6];
    float* out = (float*)d_out;

    cudaFuncSetAttribute(discovery_hmma,
                         cudaFuncAttributeMaxDynamicSharedMemorySize, (int)sizeof(Smem));

    init_out_kernel<<<1, NBATCH>>>(out, b3);
    prep_kernel<<<64, 256>>>(W2);
    discovery_hmma<<<NTILES, THREADS, sizeof(Smem)>>>(pos, W1, b1, b2, W3, out);
}

// round 7
// speedup vs baseline: 3.8702x; 1.7145x over previous
#include <cuda_runtime.h>
#include <cuda_bf16.h>
#include <cstdint>

#define NPTS 512
#define HDIM 128
#define TP 128
#define NPAIRS 130816
#define NTILES 1022
#define NBATCH 8
#define THREADS 256
#define BSTRIDE 136   // bf16 per B row (272B, conflict-free ldsm)

struct Smem {
    __nv_bfloat16 bhi[HDIM * BSTRIDE];   // W2^T hi bf16  [d][k]
    __nv_bfloat16 blo[HDIM * BSTRIDE];   // W2^T lo bf16  [d][k]
    float w1s[3 * HDIM];
    float b1s[HDIM];
    float b2s[HDIM];
    float w3s[HDIM];
    float red[NBATCH][8];
};

__device__ __align__(16) __nv_bfloat16 g_bhi[HDIM * BSTRIDE];
__device__ __align__(16) __nv_bfloat16 g_blo[HDIM * BSTRIDE];

// ---------------- f32x2 packed helpers ----------------
__device__ __forceinline__ uint64_t pk2(float a, float b) {
    uint64_t r; asm("mov.b64 %0, {%1,%2};" : "=l"(r) : "f"(a), "f"(b)); return r;
}
__device__ __forceinline__ void upk2(uint64_t v, float& a, float& b) {
    asm("mov.b64 {%0,%1}, %2;" : "=f"(a), "=f"(b) : "l"(v));
}
__device__ __forceinline__ uint64_t fma2(uint64_t a, uint64_t b, uint64_t c) {
    uint64_t d; asm("fma.rn.f32x2 %0, %1, %2, %3;" : "=l"(d) : "l"(a), "l"(b), "l"(c)); return d;
}
__device__ __forceinline__ uint64_t mul2(uint64_t a, uint64_t b) {
    uint64_t d; asm("mul.rn.f32x2 %0, %1, %2;" : "=l"(d) : "l"(a), "l"(b)); return d;
}
__device__ __forceinline__ uint64_t add2(uint64_t a, uint64_t b) {
    uint64_t d; asm("add.rn.f32x2 %0, %1, %2;" : "=l"(d) : "l"(a), "l"(b)); return d;
}
#define ONE2  0x3F8000003F800000ULL
#define MONE2 0xBF800000BF800000ULL
#define TWO2  0x4000000040000000ULL
#define MAGIC2 0x7EF311C37EF311C3ULL

__device__ __forceinline__ uint32_t pack_bf16(float lo, float hi) {
    uint32_t r;
    asm("cvt.rn.bf16x2.f32 %0, %1, %2;" : "=r"(r) : "f"(hi), "f"(lo));
    return r;
}

// fast silu for A-path (result rounded to bf16 anyway): 1 tanh MUFU + 2 FMA ops per value
__device__ __forceinline__ uint32_t silu2_tanh_bf16(uint64_t z2) {
    float z0, z1; upk2(z2, z0, z1);
    float h0 = 0.5f * z0, h1 = 0.5f * z1;
    float t0, t1;
    asm("tanh.approx.f32 %0, %1;" : "=f"(t0) : "f"(h0));
    asm("tanh.approx.f32 %0, %1;" : "=f"(t1) : "f"(h1));
    return pack_bf16(fmaf(h0, t0, h0), fmaf(h1, t1, h1));
}

// precise packed silu for epilogue: exp + bit-trick recip + 2 Newton (error ~1e-6)
__device__ __forceinline__ uint64_t silu2(uint64_t z2) {
    float z0, z1; upk2(z2, z0, z1);
    float t0 = __expf(-fabsf(z0));
    float t1 = __expf(-fabsf(z1));
    uint64_t t2 = pk2(t0, t1);
    uint64_t x2 = add2(t2, ONE2);          // 1+t in (1,2]
    uint64_t r2 = MAGIC2 - x2;             // per-half bit-trick recip (halves < 0x40000001, no borrow)
    uint64_t nx2 = fma2(t2, MONE2, MONE2); // -(1+t)
    r2 = mul2(r2, fma2(nx2, r2, TWO2));
    r2 = mul2(r2, fma2(nx2, r2, TWO2));
    uint64_t tr2 = mul2(t2, r2);
    float ra, rb, ta, tb;
    upk2(r2, ra, rb); upk2(tr2, ta, tb);
    float s0 = (z0 >= 0.0f) ? ra : ta;
    float s1 = (z1 >= 0.0f) ? rb : tb;
    return pk2(z0 * s0, z1 * s1);
}

__device__ __forceinline__ void ldsm_x4(uint32_t& r0, uint32_t& r1, uint32_t& r2, uint32_t& r3,
                                        uint32_t addr) {
    asm volatile("ldmatrix.sync.aligned.m8n8.x4.shared.b16 {%0,%1,%2,%3}, [%4];"
                 : "=r"(r0), "=r"(r1), "=r"(r2), "=r"(r3) : "r"(addr));
}
__device__ __forceinline__ void mma_bf16(float* c, const uint32_t* a, uint32_t b0, uint32_t b1) {
    asm volatile(
        "mma.sync.aligned.m16n8k16.row.col.f32.bf16.bf16.f32 "
        "{%0,%1,%2,%3}, {%4,%5,%6,%7}, {%8,%9}, {%0,%1,%2,%3};"
        : "+f"(c[0]), "+f"(c[1]), "+f"(c[2]), "+f"(c[3])
        : "r"(a[0]), "r"(a[1]), "r"(a[2]), "r"(a[3]), "r"(b0), "r"(b1));
}
__device__ __forceinline__ uint32_t smem_u32(const void* p) {
    uint32_t a;
    asm("{ .reg .u64 t; cvta.to.shared.u64 t, %1; cvt.u32.u64 %0, t; }" : "=r"(a) : "l"(p));
    return a;
}

// ---------------- kernels ----------------
__global__ void init_out_kernel(float* out, const float* b3) {
    int b = threadIdx.x;
    if (b < NBATCH) out[b] = (float)NPAIRS * b3[0];
}

__global__ void prep_kernel(const float* __restrict__ W2) {
    int idx = blockIdx.x * blockDim.x + threadIdx.x;
    if (idx >= HDIM * HDIM) return;
    int d = idx & 127;
    int k = idx >> 7;
    float v = W2[idx];                        // W2[k][d] -> B[d][k]
    __nv_bfloat16 hi = __float2bfloat16(v);
    float lo = v - __bfloat162float(hi);
    g_bhi[d * BSTRIDE + k] = hi;
    g_blo[d * BSTRIDE + k] = __float2bfloat16(lo);
}

__global__ __launch_bounds__(THREADS, 2)
void discovery_hmma(const float* __restrict__ pos,
                    const float* __restrict__ W1,
                    const float* __restrict__ b1,
                    const float* __restrict__ b2,
                    const float* __restrict__ W3,
                    float* __restrict__ out) {
    extern __shared__ char smem_raw[];
    Smem* s = reinterpret_cast<Smem*>(smem_raw);

    const int t = threadIdx.x;
    const int w = t >> 5;
    const int lane = t & 31;
    const int tile = blockIdx.x;

    // ---- stage weights ----
    {
        const uint4* shi = (const uint4*)g_bhi;
        const uint4* slo = (const uint4*)g_blo;
        uint4* dhi = (uint4*)s->bhi;
        uint4* dlo = (uint4*)s->blo;
        for (int i = t; i < (HDIM * BSTRIDE) / 8; i += THREADS) {
            dhi[i] = shi[i];
            dlo[i] = slo[i];
        }
    }
    for (int i = t; i < 3 * HDIM; i += THREADS) s->w1s[i] = W1[i];
    if (t < HDIM) {
        s->b1s[t] = b1[t];
        s->b2s[t] = b2[t];
        s->w3s[t] = W3[t];
    }

    // ---- pair decode: 2 pairs per thread (rows r, r+8 of this warp's 16) ----
    int ip[2], jp[2];
    {
        const int mrow = w * 16 + (lane >> 2);
        #pragma unroll
        for (int q = 0; q < 2; ++q) {
            int p = tile * TP + mrow + q * 8;
            double tn = 2.0 * NPTS - 1.0;
            int i = (int)floor((tn - sqrt(tn * tn - 8.0 * (double)p)) * 0.5);
            if (i < 0) i = 0;
            while ((long)(i + 1) * (2 * NPTS - 1 - (i + 1)) / 2 <= p) i++;
            while ((long)i * (2 * NPTS - 1 - i) / 2 > p) i--;
            long s0 = (long)i * (2 * NPTS - 1 - i) / 2;
            ip[q] = i;
            jp[q] = i + 1 + (int)(p - s0);
        }
    }
    __syncthreads();

    const uint32_t bhi_base = smem_u32(s->bhi);
    const uint32_t blo_base = smem_u32(s->blo);
    const int rowoff = (lane & 7) + ((lane >> 4) << 3);
    const int kadd   = ((lane >> 3) & 1) << 3;
    const uint32_t laneB = (uint32_t)(rowoff * BSTRIDE + kadd) * 2u;
    const int kcol = (lane & 3) * 2;

    for (int b = 0; b < NBATCH; ++b) {
        // ---- features (packed broadcasts per pair) ----
        uint64_t F0[2], F1[2], F2[2];
        {
            const float* pb = pos + (size_t)b * NPTS * 3;
            #pragma unroll
            for (int q = 0; q < 2; ++q) {
                int i = ip[q], j = jp[q];
                float dx = pb[i * 3 + 0] - pb[j * 3 + 0];
                float dy = pb[i * 3 + 1] - pb[j * 3 + 1];
                float dz = pb[i * 3 + 2] - pb[j * 3 + 2];
                float r = sqrtf(dx * dx + dy * dy + dz * dz);
                r = fmaxf(r, 0.05f);
                float ri = 1.0f / r;
                F0[q] = pk2(r, r);
                F1[q] = pk2(ri, ri);
                F2[q] = pk2(ri * ri, ri * ri);
            }
        }

        float acc[16][4];
        #pragma unroll
        for (int nt = 0; nt < 16; ++nt)
            #pragma unroll
            for (int e = 0; e < 4; ++e) acc[nt][e] = 0.0f;

        // ---- mainloop: 8 k-steps; A in registers; B = hi + lo chains ----
        #pragma unroll
        for (int ks = 0; ks < 8; ++ks) {
            const int k0 = ks * 16 + kcol;
            float2 va0 = *(const float2*)&s->w1s[k0];
            float2 va8 = *(const float2*)&s->w1s[k0 + 8];
            float2 vb0 = *(const float2*)&s->w1s[128 + k0];
            float2 vb8 = *(const float2*)&s->w1s[128 + k0 + 8];
            float2 vc0 = *(const float2*)&s->w1s[256 + k0];
            float2 vc8 = *(const float2*)&s->w1s[256 + k0 + 8];
            float2 vd0 = *(const float2*)&s->b1s[k0];
            float2 vd8 = *(const float2*)&s->b1s[k0 + 8];
            uint64_t wa0 = pk2(va0.x, va0.y), wa8 = pk2(va8.x, va8.y);
            uint64_t wb0 = pk2(vb0.x, vb0.y), wb8 = pk2(vb8.x, vb8.y);
            uint64_t wc0 = pk2(vc0.x, vc0.y), wc8 = pk2(vc8.x, vc8.y);
            uint64_t bb0 = pk2(vd0.x, vd0.y), bb8 = pk2(vd8.x, vd8.y);

            uint32_t afr[4];
            {
                uint64_t z00 = fma2(wc0, F2[0], fma2(wb0, F1[0], fma2(wa0, F0[0], bb0)));
                uint64_t z10 = fma2(wc0, F2[1], fma2(wb0, F1[1], fma2(wa0, F0[1], bb0)));
                uint64_t z08 = fma2(wc8, F2[0], fma2(wb8, F1[0], fma2(wa8, F0[0], bb8)));
                uint64_t z18 = fma2(wc8, F2[1], fma2(wb8, F1[1], fma2(wa8, F0[1], bb8)));
                afr[0] = silu2_tanh_bf16(z00);   // (q0; k0,k0+1)
                afr[1] = silu2_tanh_bf16(z10);   // (q1; k0,k0+1)
                afr[2] = silu2_tanh_bf16(z08);   // (q0; k0+8,k0+9)
                afr[3] = silu2_tanh_bf16(z18);   // (q1; k0+8,k0+9)
            }

            #pragma unroll
            for (int pr = 0; pr < 8; ++pr) {
                const uint32_t off = (uint32_t)((pr * 16) * BSTRIDE + ks * 16) * 2u + laneB;
                uint32_t h0, h1v, h2v, h3v, l0, l1v, l2v, l3v;
                ldsm_x4(h0, h1v, h2v, h3v, bhi_base + off);
                ldsm_x4(l0, l1v, l2v, l3v, blo_base + off);
                mma_bf16(acc[pr * 2],     afr, h0,  h1v);
                mma_bf16(acc[pr * 2 + 1], afr, h2v, h3v);
                mma_bf16(acc[pr * 2],     afr, l0,  l1v);
                mma_bf16(acc[pr * 2 + 1], afr, l2v, l3v);
            }
        }

        // ---- epilogue (packed precise silu) ----
        uint64_t sum2 = 0;
        #pragma unroll
        for (int nt = 0; nt < 16; ++nt) {
            int col = nt * 8 + kcol;
            float2 b2p = *(const float2*)&s->b2s[col];
            float2 w3p = *(const float2*)&s->w3s[col];
            uint64_t b2v = pk2(b2p.x, b2p.y);
            uint64_t w3v = pk2(w3p.x, w3p.y);
            uint64_t za = add2(pk2(acc[nt][0], acc[nt][1]), b2v);
            uint64_t zb = add2(pk2(acc[nt][2], acc[nt][3]), b2v);
            sum2 = fma2(silu2(za), w3v, sum2);
            sum2 = fma2(silu2(zb), w3v, sum2);
        }
        float sa, sb;
        upk2(sum2, sa, sb);
        float sum = sa + sb;

        #pragma unroll
        for (int off = 16; off > 0; off >>= 1)
            sum += __shfl_xor_sync(0xFFFFFFFFu, sum, off);
        if (lane == 0) s->red[b][w] = sum;
    }

    __syncthreads();
    if (w == 0 && lane < NBATCH) {
        float tot = 0.0f;
        #pragma unroll
        for (int wi = 0; wi < 8; ++wi) tot += s->red[lane][wi];
        atomicAdd(&out[lane], tot);
    }
}

extern "C" void kernel_launch(void* const* d_in, const int* in_sizes, int n_in,
                              void* d_out, int out_size) {
    const float* pos = (const float*)d_in[0];
    const float* W1  = (const float*)d_in[1];
    const float* b1  = (const float*)d_in[2];
    const float* W2  = (const float*)d_in[3];
    const float* b2  = (const float*)d_in[4];
    const float* W3  = (const float*)d_in[5];
    const float* b3  = (const float*)d_in[6];
    float* out = (float*)d_out;

    cudaFuncSetAttribute(discovery_hmma,
                         cudaFuncAttributeMaxDynamicSharedMemorySize, (int)sizeof(Smem));

    init_out_kernel<<<1, NBATCH>>>(out, b3);
    prep_kernel<<<64, 256>>>(W2);
    discovery_hmma<<<NTILES, THREADS, sizeof(Smem)>>>(pos, W1, b1, b2, W3, out);
}

// round 9
// speedup vs baseline: 4.9641x; 1.2826x over previous
#include <cuda_runtime.h>
#include <cuda_fp16.h>
#include <cstdint>

#define NPTS 512
#define HDIM 128
#define TP 128
#define NPAIRS 130816
#define NTILES 1022
#define NBATCH 8
#define NB_BLK 4          // batches per block
#define GRIDY (NBATCH / NB_BLK)
#define THREADS 256
#define BSTRIDE 136       // fp16 per B row (272B, conflict-free ldsm)

struct Smem {
    __half bmat[HDIM * BSTRIDE];   // W2^T fp16  [d][k]
    float w1s[3 * HDIM];
    float b1s[HDIM];
    float b2s[HDIM];
    float w3s[HDIM];
    float red[NB_BLK][8];
};

__device__ __align__(16) __half g_bmat[HDIM * BSTRIDE];

// ---------------- f32x2 packed helpers ----------------
__device__ __forceinline__ uint64_t pk2(float a, float b) {
    uint64_t r; asm("mov.b64 %0, {%1,%2};" : "=l"(r) : "f"(a), "f"(b)); return r;
}
__device__ __forceinline__ void upk2(uint64_t v, float& a, float& b) {
    asm("mov.b64 {%0,%1}, %2;" : "=f"(a), "=f"(b) : "l"(v));
}
__device__ __forceinline__ uint64_t fma2(uint64_t a, uint64_t b, uint64_t c) {
    uint64_t d; asm("fma.rn.f32x2 %0, %1, %2, %3;" : "=l"(d) : "l"(a), "l"(b), "l"(c)); return d;
}
__device__ __forceinline__ uint64_t mul2(uint64_t a, uint64_t b) {
    uint64_t d; asm("mul.rn.f32x2 %0, %1, %2;" : "=l"(d) : "l"(a), "l"(b)); return d;
}
__device__ __forceinline__ uint64_t add2(uint64_t a, uint64_t b) {
    uint64_t d; asm("add.rn.f32x2 %0, %1, %2;" : "=l"(d) : "l"(a), "l"(b)); return d;
}
#define ONE2  0x3F8000003F800000ULL
#define MONE2 0xBF800000BF800000ULL
#define TWO2  0x4000000040000000ULL
#define MAGIC2 0x7EF311C37EF311C3ULL

// pack (lo, hi) floats into f16x2
__device__ __forceinline__ uint32_t pack_f16(float lo, float hi) {
    uint32_t r;
    asm("cvt.rn.f16x2.f32 %0, %1, %2;" : "=r"(r) : "f"(hi), "f"(lo));
    return r;
}

// fast silu for A-path (result rounded to fp16): 1 tanh MUFU + 2 FMA ops per value
__device__ __forceinline__ uint32_t silu2_tanh_f16(uint64_t z2) {
    float z0, z1; upk2(z2, z0, z1);
    float h0 = 0.5f * z0, h1 = 0.5f * z1;
    float t0, t1;
    asm("tanh.approx.f32 %0, %1;" : "=f"(t0) : "f"(h0));
    asm("tanh.approx.f32 %0, %1;" : "=f"(t1) : "f"(h1));
    return pack_f16(fmaf(h0, t0, h0), fmaf(h1, t1, h1));
}

// precise packed silu for epilogue: exp + bit-trick recip + 2 Newton (error ~1e-6)
__device__ __forceinline__ uint64_t silu2(uint64_t z2) {
    float z0, z1; upk2(z2, z0, z1);
    float t0 = __expf(-fabsf(z0));
    float t1 = __expf(-fabsf(z1));
    uint64_t t2 = pk2(t0, t1);
    uint64_t x2 = add2(t2, ONE2);
    uint64_t r2 = MAGIC2 - x2;
    uint64_t nx2 = fma2(t2, MONE2, MONE2);
    r2 = mul2(r2, fma2(nx2, r2, TWO2));
    r2 = mul2(r2, fma2(nx2, r2, TWO2));
    uint64_t tr2 = mul2(t2, r2);
    float ra, rb, ta, tb;
    upk2(r2, ra, rb); upk2(tr2, ta, tb);
    float s0 = (z0 >= 0.0f) ? ra : ta;
    float s1 = (z1 >= 0.0f) ? rb : tb;
    return pk2(z0 * s0, z1 * s1);
}

__device__ __forceinline__ void ldsm_x4(uint32_t& r0, uint32_t& r1, uint32_t& r2, uint32_t& r3,
                                        uint32_t addr) {
    asm volatile("ldmatrix.sync.aligned.m8n8.x4.shared.b16 {%0,%1,%2,%3}, [%4];"
                 : "=r"(r0), "=r"(r1), "=r"(r2), "=r"(r3) : "r"(addr));
}
__device__ __forceinline__ void mma_f16(float* c, const uint32_t* a, uint32_t b0, uint32_t b1) {
    asm volatile(
        "mma.sync.aligned.m16n8k16.row.col.f32.f16.f16.f32 "
        "{%0,%1,%2,%3}, {%4,%5,%6,%7}, {%8,%9}, {%0,%1,%2,%3};"
        : "+f"(c[0]), "+f"(c[1]), "+f"(c[2]), "+f"(c[3])
        : "r"(a[0]), "r"(a[1]), "r"(a[2]), "r"(a[3]), "r"(b0), "r"(b1));
}
__device__ __forceinline__ uint32_t smem_u32(const void* p) {
    uint32_t a;
    asm("{ .reg .u64 t; cvta.to.shared.u64 t, %1; cvt.u32.u64 %0, t; }" : "=r"(a) : "l"(p));
    return a;
}

// ---------------- kernels ----------------
__global__ void init_out_kernel(float* out, const float* b3) {
    int b = threadIdx.x;
    if (b < NBATCH) out[b] = (float)NPAIRS * b3[0];
}

__global__ void prep_kernel(const float* __restrict__ W2) {
    int idx = blockIdx.x * blockDim.x + threadIdx.x;
    if (idx >= HDIM * HDIM) return;
    int d = idx & 127;
    int k = idx >> 7;
    g_bmat[d * BSTRIDE + k] = __float2half(W2[idx]);   // W2[k][d] -> B[d][k]
}

__global__ __launch_bounds__(THREADS, 2)
void discovery_hmma(const float* __restrict__ pos,
                    const float* __restrict__ W1,
                    const float* __restrict__ b1,
                    const float* __restrict__ b2,
                    const float* __restrict__ W3,
                    float* __restrict__ out) {
    extern __shared__ char smem_raw[];
    Smem* s = reinterpret_cast<Smem*>(smem_raw);

    const int t = threadIdx.x;
    const int w = t >> 5;
    const int lane = t & 31;
    const int tile = blockIdx.x;
    const int b0 = blockIdx.y * NB_BLK;

    // ---- stage weights ----
    {
        const uint4* src = (const uint4*)g_bmat;
        uint4* dst = (uint4*)s->bmat;
        for (int i = t; i < (HDIM * BSTRIDE) / 8; i += THREADS) dst[i] = src[i];
    }
    for (int i = t; i < 3 * HDIM; i += THREADS) s->w1s[i] = W1[i];
    if (t < HDIM) {
        s->b1s[t] = b1[t];
        s->b2s[t] = b2[t];
        s->w3s[t] = W3[t];
    }

    // ---- pair decode: 2 pairs per thread (rows r, r+8 of this warp's 16) ----
    int ip[2], jp[2];
    {
        const int mrow = w * 16 + (lane >> 2);
        #pragma unroll
        for (int q = 0; q < 2; ++q) {
            int p = tile * TP + mrow + q * 8;
            double tn = 2.0 * NPTS - 1.0;
            int i = (int)floor((tn - sqrt(tn * tn - 8.0 * (double)p)) * 0.5);
            if (i < 0) i = 0;
            while ((long)(i + 1) * (2 * NPTS - 1 - (i + 1)) / 2 <= p) i++;
            while ((long)i * (2 * NPTS - 1 - i) / 2 > p) i--;
            long s0 = (long)i * (2 * NPTS - 1 - i) / 2;
            ip[q] = i;
            jp[q] = i + 1 + (int)(p - s0);
        }
    }
    __syncthreads();

    const uint32_t b_base = smem_u32(s->bmat);
    const int rowoff = (lane & 7) + ((lane >> 4) << 3);
    const int kadd   = ((lane >> 3) & 1) << 3;
    const uint32_t laneB = (uint32_t)(rowoff * BSTRIDE + kadd) * 2u;
    const int kcol = (lane & 3) * 2;

    for (int bb = 0; bb < NB_BLK; ++bb) {
        const int b = b0 + bb;
        // ---- features (packed broadcasts per pair) ----
        uint64_t F0[2], F1[2], F2[2];
        {
            const float* pb = pos + (size_t)b * NPTS * 3;
            #pragma unroll
            for (int q = 0; q < 2; ++q) {
                int i = ip[q], j = jp[q];
                float dx = pb[i * 3 + 0] - pb[j * 3 + 0];
                float dy = pb[i * 3 + 1] - pb[j * 3 + 1];
                float dz = pb[i * 3 + 2] - pb[j * 3 + 2];
                float r = sqrtf(dx * dx + dy * dy + dz * dz);
                r = fmaxf(r, 0.05f);
                float ri = 1.0f / r;
                F0[q] = pk2(r, r);
                F1[q] = pk2(ri, ri);
                F2[q] = pk2(ri * ri, ri * ri);
            }
        }

        float acc[16][4];
        #pragma unroll
        for (int nt = 0; nt < 16; ++nt)
            #pragma unroll
            for (int e = 0; e < 4; ++e) acc[nt][e] = 0.0f;

        // ---- mainloop: 8 k-steps; A in registers; single fp16 chain ----
        #pragma unroll
        for (int ks = 0; ks < 8; ++ks) {
            const int k0 = ks * 16 + kcol;
            float2 va0 = *(const float2*)&s->w1s[k0];
            float2 va8 = *(const float2*)&s->w1s[k0 + 8];
            float2 vb0 = *(const float2*)&s->w1s[128 + k0];
            float2 vb8 = *(const float2*)&s->w1s[128 + k0 + 8];
            float2 vc0 = *(const float2*)&s->w1s[256 + k0];
            float2 vc8 = *(const float2*)&s->w1s[256 + k0 + 8];
            float2 vd0 = *(const float2*)&s->b1s[k0];
            float2 vd8 = *(const float2*)&s->b1s[k0 + 8];
            uint64_t wa0 = pk2(va0.x, va0.y), wa8 = pk2(va8.x, va8.y);
            uint64_t wb0 = pk2(vb0.x, vb0.y), wb8 = pk2(vb8.x, vb8.y);
            uint64_t wc0 = pk2(vc0.x, vc0.y), wc8 = pk2(vc8.x, vc8.y);
            uint64_t bbv0 = pk2(vd0.x, vd0.y), bbv8 = pk2(vd8.x, vd8.y);

            uint32_t afr[4];
            {
                uint64_t z00 = fma2(wc0, F2[0], fma2(wb0, F1[0], fma2(wa0, F0[0], bbv0)));
                uint64_t z10 = fma2(wc0, F2[1], fma2(wb0, F1[1], fma2(wa0, F0[1], bbv0)));
                uint64_t z08 = fma2(wc8, F2[0], fma2(wb8, F1[0], fma2(wa8, F0[0], bbv8)));
                uint64_t z18 = fma2(wc8, F2[1], fma2(wb8, F1[1], fma2(wa8, F0[1], bbv8)));
                afr[0] = silu2_tanh_f16(z00);   // (q0; k0,k0+1)
                afr[1] = silu2_tanh_f16(z10);   // (q1; k0,k0+1)
                afr[2] = silu2_tanh_f16(z08);   // (q0; k0+8,k0+9)
                afr[3] = silu2_tanh_f16(z18);   // (q1; k0+8,k0+9)
            }

            #pragma unroll
            for (int pr = 0; pr < 8; ++pr) {
                const uint32_t off = (uint32_t)((pr * 16) * BSTRIDE + ks * 16) * 2u + laneB;
                uint32_t h0, h1v, h2v, h3v;
                ldsm_x4(h0, h1v, h2v, h3v, b_base + off);
                mma_f16(acc[pr * 2],     afr, h0,  h1v);
                mma_f16(acc[pr * 2 + 1], afr, h2v, h3v);
            }
        }

        // ---- epilogue (packed precise silu) ----
        uint64_t sum2 = 0;
        #pragma unroll
        for (int nt = 0; nt < 16; ++nt) {
            int col = nt * 8 + kcol;
            float2 b2p = *(const float2*)&s->b2s[col];
            float2 w3p = *(const float2*)&s->w3s[col];
            uint64_t b2v = pk2(b2p.x, b2p.y);
            uint64_t w3v = pk2(w3p.x, w3p.y);
            uint64_t za = add2(pk2(acc[nt][0], acc[nt][1]), b2v);
            uint64_t zb = add2(pk2(acc[nt][2], acc[nt][3]), b2v);
            sum2 = fma2(silu2(za), w3v, sum2);
            sum2 = fma2(silu2(zb), w3v, sum2);
        }
        float sa, sb;
        upk2(sum2, sa, sb);
        float sum = sa + sb;

        #pragma unroll
        for (int off = 16; off > 0; off >>= 1)
            sum += __shfl_xor_sync(0xFFFFFFFFu, sum, off);
        if (lane == 0) s->red[bb][w] = sum;
    }

    __syncthreads();
    if (w == 0 && lane < NB_BLK) {
        float tot = 0.0f;
        #pragma unroll
        for (int wi = 0; wi < 8; ++wi) tot += s->red[lane][wi];
        atomicAdd(&out[b0 + lane], tot);
    }
}

extern "C" void kernel_launch(void* const* d_in, const int* in_sizes, int n_in,
                              void* d_out, int out_size) {
    const float* pos = (const float*)d_in[0];
    const float* W1  = (const float*)d_in[1];
    const float* b1  = (const float*)d_in[2];
    const float* W2  = (const float*)d_in[3];
    const float* b2  = (const float*)d_in[4];
    const float* W3  = (const float*)d_in[5];
    const float* b3  = (const float*)d_in[6];
    float* out = (float*)d_out;

    cudaFuncSetAttribute(discovery_hmma,
                         cudaFuncAttributeMaxDynamicSharedMemorySize, (int)sizeof(Smem));

    init_out_kernel<<<1, NBATCH>>>(out, b3);
    prep_kernel<<<64, 256>>>(W2);
    dim3 grid(NTILES, GRIDY);
    discovery_hmma<<<grid, THREADS, sizeof(Smem)>>>(pos, W1, b1, b2, W3, out);
}

// round 11
// speedup vs baseline: 6.1935x; 1.2477x over previous
#include <cuda_runtime.h>
#include <cuda_fp16.h>
#include <cstdint>

#define NPTS 512
#define HDIM 128
#define TP 128
#define NPAIRS 130816
#define NTILES 1022
#define NBATCH 8
#define NB_BLK 4
#define GRIDY (NBATCH / NB_BLK)
#define THREADS 256
#define BSTRIDE 136       // fp16 per B row (272B, conflict-free ldsm)

struct Smem {
    __half bmat[HDIM * BSTRIDE];   // W2^T fp16  [d][k]
    float w1s[3 * HDIM];
    float b1s[HDIM];
    float b2s[HDIM];
    float w3s[HDIM];
    float red[NB_BLK][8];
};

__device__ __align__(16) __half g_bmat[HDIM * BSTRIDE];

// ---------------- f32x2 packed helpers ----------------
__device__ __forceinline__ uint64_t pk2(float a, float b) {
    uint64_t r; asm("mov.b64 %0, {%1,%2};" : "=l"(r) : "f"(a), "f"(b)); return r;
}
__device__ __forceinline__ void upk2(uint64_t v, float& a, float& b) {
    asm("mov.b64 {%0,%1}, %2;" : "=f"(a), "=f"(b) : "l"(v));
}
__device__ __forceinline__ uint64_t fma2(uint64_t a, uint64_t b, uint64_t c) {
    uint64_t d; asm("fma.rn.f32x2 %0, %1, %2, %3;" : "=l"(d) : "l"(a), "l"(b), "l"(c)); return d;
}
__device__ __forceinline__ uint64_t add2(uint64_t a, uint64_t b) {
    uint64_t d; asm("add.rn.f32x2 %0, %1, %2;" : "=l"(d) : "l"(a), "l"(b)); return d;
}

// pack (lo, hi) floats into f16x2
__device__ __forceinline__ uint32_t pack_f16(float lo, float hi) {
    uint32_t r;
    asm("cvt.rn.f16x2.f32 %0, %1, %2;" : "=r"(r) : "f"(hi), "f"(lo));
    return r;
}

// silu(z) = z * sigmoid(z) = 0.5z*tanh(z/2) + 0.5z ; 1 MUFU + 2 FMA per value
__device__ __forceinline__ uint32_t silu2_tanh_f16(uint64_t z2) {
    float z0, z1; upk2(z2, z0, z1);
    float h0 = 0.5f * z0, h1 = 0.5f * z1;
    float t0, t1;
    asm("tanh.approx.f32 %0, %1;" : "=f"(t0) : "f"(h0));
    asm("tanh.approx.f32 %0, %1;" : "=f"(t1) : "f"(h1));
    return pack_f16(fmaf(h0, t0, h0), fmaf(h1, t1, h1));
}

// epilogue silu (fp32 packed result), same tanh form
__device__ __forceinline__ uint64_t silu2_tanh(uint64_t z2) {
    float z0, z1; upk2(z2, z0, z1);
    float h0 = 0.5f * z0, h1 = 0.5f * z1;
    float t0, t1;
    asm("tanh.approx.f32 %0, %1;" : "=f"(t0) : "f"(h0));
    asm("tanh.approx.f32 %0, %1;" : "=f"(t1) : "f"(h1));
    return pk2(fmaf(h0, t0, h0), fmaf(h1, t1, h1));
}

__device__ __forceinline__ void ldsm_x4(uint32_t& r0, uint32_t& r1, uint32_t& r2, uint32_t& r3,
                                        uint32_t addr) {
    asm volatile("ldmatrix.sync.aligned.m8n8.x4.shared.b16 {%0,%1,%2,%3}, [%4];"
                 : "=r"(r0), "=r"(r1), "=r"(r2), "=r"(r3) : "r"(addr));
}
__device__ __forceinline__ void mma_f16(float* c, const uint32_t* a, uint32_t b0, uint32_t b1) {
    asm volatile(
        "mma.sync.aligned.m16n8k16.row.col.f32.f16.f16.f32 "
        "{%0,%1,%2,%3}, {%4,%5,%6,%7}, {%8,%9}, {%0,%1,%2,%3};"
        : "+f"(c[0]), "+f"(c[1]), "+f"(c[2]), "+f"(c[3])
        : "r"(a[0]), "r"(a[1]), "r"(a[2]), "r"(a[3]), "r"(b0), "r"(b1));
}
__device__ __forceinline__ uint32_t smem_u32(const void* p) {
    uint32_t a;
    asm("{ .reg .u64 t; cvta.to.shared.u64 t, %1; cvt.u32.u64 %0, t; }" : "=r"(a) : "l"(p));
    return a;
}

// ---------------- kernels ----------------
__global__ void init_out_kernel(float* out, const float* b3) {
    int b = threadIdx.x;
    if (b < NBATCH) out[b] = (float)NPAIRS * b3[0];
}

__global__ void prep_kernel(const float* __restrict__ W2) {
    int idx = blockIdx.x * blockDim.x + threadIdx.x;
    if (idx >= HDIM * HDIM) return;
    int d = idx & 127;
    int k = idx >> 7;
    g_bmat[d * BSTRIDE + k] = __float2half(W2[idx]);   // W2[k][d] -> B[d][k]
}

__global__ __launch_bounds__(THREADS, 2)
void discovery_hmma(const float* __restrict__ pos,
                    const float* __restrict__ W1,
                    const float* __restrict__ b1,
                    const float* __restrict__ b2,
                    const float* __restrict__ W3,
                    float* __restrict__ out) {
    extern __shared__ char smem_raw[];
    Smem* s = reinterpret_cast<Smem*>(smem_raw);

    const int t = threadIdx.x;
    const int w = t >> 5;
    const int lane = t & 31;
    const int tile = blockIdx.x;
    const int b0 = blockIdx.y * NB_BLK;

    // ---- stage weights ----
    {
        const uint4* src = (const uint4*)g_bmat;
        uint4* dst = (uint4*)s->bmat;
        for (int i = t; i < (HDIM * BSTRIDE) / 8; i += THREADS) dst[i] = src[i];
    }
    for (int i = t; i < 3 * HDIM; i += THREADS) s->w1s[i] = W1[i];
    if (t < HDIM) {
        s->b1s[t] = b1[t];
        s->b2s[t] = b2[t];
        s->w3s[t] = W3[t];
    }

    // ---- pair decode: 2 pairs per thread (rows r, r+8 of this warp's 16) ----
    int ip[2], jp[2];
    {
        const int mrow = w * 16 + (lane >> 2);
        #pragma unroll
        for (int q = 0; q < 2; ++q) {
            int p = tile * TP + mrow + q * 8;
            double tn = 2.0 * NPTS - 1.0;
            int i = (int)floor((tn - sqrt(tn * tn - 8.0 * (double)p)) * 0.5);
            if (i < 0) i = 0;
            while ((long)(i + 1) * (2 * NPTS - 1 - (i + 1)) / 2 <= p) i++;
            while ((long)i * (2 * NPTS - 1 - i) / 2 > p) i--;
            long s0 = (long)i * (2 * NPTS - 1 - i) / 2;
            ip[q] = i;
            jp[q] = i + 1 + (int)(p - s0);
        }
    }
    __syncthreads();

    const uint32_t b_base = smem_u32(s->bmat);
    const int rowoff = (lane & 7) + ((lane >> 4) << 3);
    const int kadd   = ((lane >> 3) & 1) << 3;
    const uint32_t laneB = (uint32_t)(rowoff * BSTRIDE + kadd) * 2u + b_base;
    const int kcol = (lane & 3) * 2;

    for (int bb = 0; bb < NB_BLK; ++bb) {
        const int b = b0 + bb;

        // ---- features ----
        uint64_t F0[2], F1[2], F2[2];
        {
            const float* pb = pos + (size_t)b * NPTS * 3;
            #pragma unroll
            for (int q = 0; q < 2; ++q) {
                int i = ip[q], j = jp[q];
                float dx = pb[i * 3 + 0] - pb[j * 3 + 0];
                float dy = pb[i * 3 + 1] - pb[j * 3 + 1];
                float dz = pb[i * 3 + 2] - pb[j * 3 + 2];
                float r = sqrtf(dx * dx + dy * dy + dz * dz);
                r = fmaxf(r, 0.05f);
                float ri = 1.0f / r;
                F0[q] = pk2(r, r);
                F1[q] = pk2(ri, ri);
                F2[q] = pk2(ri * ri, ri * ri);
            }
        }

        // ---- build ALL A fragments for this batch (8 k-steps x 4 regs) ----
        uint32_t afr[8][4];
        #pragma unroll
        for (int ks = 0; ks < 8; ++ks) {
            const int k0 = ks * 16 + kcol;
            float2 va0 = *(const float2*)&s->w1s[k0];
            float2 va8 = *(const float2*)&s->w1s[k0 + 8];
            float2 vb0 = *(const float2*)&s->w1s[128 + k0];
            float2 vb8 = *(const float2*)&s->w1s[128 + k0 + 8];
            float2 vc0 = *(const float2*)&s->w1s[256 + k0];
            float2 vc8 = *(const float2*)&s->w1s[256 + k0 + 8];
            float2 vd0 = *(const float2*)&s->b1s[k0];
            float2 vd8 = *(const float2*)&s->b1s[k0 + 8];
            uint64_t wa0 = pk2(va0.x, va0.y), wa8 = pk2(va8.x, va8.y);
            uint64_t wb0 = pk2(vb0.x, vb0.y), wb8 = pk2(vb8.x, vb8.y);
            uint64_t wc0 = pk2(vc0.x, vc0.y), wc8 = pk2(vc8.x, vc8.y);
            uint64_t bbv0 = pk2(vd0.x, vd0.y), bbv8 = pk2(vd8.x, vd8.y);

            uint64_t z00 = fma2(wc0, F2[0], fma2(wb0, F1[0], fma2(wa0, F0[0], bbv0)));
            uint64_t z10 = fma2(wc0, F2[1], fma2(wb0, F1[1], fma2(wa0, F0[1], bbv0)));
            uint64_t z08 = fma2(wc8, F2[0], fma2(wb8, F1[0], fma2(wa8, F0[0], bbv8)));
            uint64_t z18 = fma2(wc8, F2[1], fma2(wb8, F1[1], fma2(wa8, F0[1], bbv8)));
            afr[ks][0] = silu2_tanh_f16(z00);   // (q0; k0,k0+1)
            afr[ks][1] = silu2_tanh_f16(z10);   // (q1; k0,k0+1)
            afr[ks][2] = silu2_tanh_f16(z08);   // (q0; k0+8,k0+9)
            afr[ks][3] = silu2_tanh_f16(z18);   // (q1; k0+8,k0+9)
        }

        // ---- per column-pair: accumulate over k, then fused epilogue ----
        uint64_t sum2 = 0;
        #pragma unroll
        for (int pr = 0; pr < 8; ++pr) {
            float acc0[4] = {0.f, 0.f, 0.f, 0.f};
            float acc1[4] = {0.f, 0.f, 0.f, 0.f};
            const uint32_t prbase = laneB + (uint32_t)((pr * 16) * BSTRIDE) * 2u;
            #pragma unroll
            for (int ks = 0; ks < 8; ++ks) {
                uint32_t h0, h1v, h2v, h3v;
                ldsm_x4(h0, h1v, h2v, h3v, prbase + (uint32_t)(ks * 16) * 2u);
                mma_f16(acc0, afr[ks], h0,  h1v);
                mma_f16(acc1, afr[ks], h2v, h3v);
            }
            // epilogue for cols pr*16 + kcol (+0/+8)
            {
                int col = pr * 16 + kcol;
                float2 b2a = *(const float2*)&s->b2s[col];
                float2 w3a = *(const float2*)&s->w3s[col];
                float2 b2b = *(const float2*)&s->b2s[col + 8];
                float2 w3b = *(const float2*)&s->w3s[col + 8];
                uint64_t b2va = pk2(b2a.x, b2a.y), w3va = pk2(w3a.x, w3a.y);
                uint64_t b2vb = pk2(b2b.x, b2b.y), w3vb = pk2(w3b.x, w3b.y);
                uint64_t za0 = add2(pk2(acc0[0], acc0[1]), b2va);
                uint64_t za1 = add2(pk2(acc0[2], acc0[3]), b2va);
                uint64_t zb0 = add2(pk2(acc1[0], acc1[1]), b2vb);
                uint64_t zb1 = add2(pk2(acc1[2], acc1[3]), b2vb);
                sum2 = fma2(silu2_tanh(za0), w3va, sum2);
                sum2 = fma2(silu2_tanh(za1), w3va, sum2);
                sum2 = fma2(silu2_tanh(zb0), w3vb, sum2);
                sum2 = fma2(silu2_tanh(zb1), w3vb, sum2);
            }
        }
        float sa, sb;
        upk2(sum2, sa, sb);
        float sum = sa + sb;

        #pragma unroll
        for (int off = 16; off > 0; off >>= 1)
            sum += __shfl_xor_sync(0xFFFFFFFFu, sum, off);
        if (lane == 0) s->red[bb][w] = sum;
    }

    __syncthreads();
    if (w == 0 && lane < NB_BLK) {
        float tot = 0.0f;
        #pragma unroll
        for (int wi = 0; wi < 8; ++wi) tot += s->red[lane][wi];
        atomicAdd(&out[b0 + lane], tot);
    }
}

extern "C" void kernel_launch(void* const* d_in, const int* in_sizes, int n_in,
                              void* d_out, int out_size) {
    const float* pos = (const float*)d_in[0];
    const float* W1  = (const float*)d_in[1];
    const float* b1  = (const float*)d_in[2];
    const float* W2  = (const float*)d_in[3];
    const float* b2  = (const float*)d_in[4];
    const float* W3  = (const float*)d_in[5];
    const float* b3  = (const float*)d_in[6];
    float* out = (float*)d_out;

    cudaFuncSetAttribute(discovery_hmma,
                         cudaFuncAttributeMaxDynamicSharedMemorySize, (int)sizeof(Smem));

    init_out_kernel<<<1, NBATCH>>>(out, b3);
    prep_kernel<<<64, 256>>>(W2);
    dim3 grid(NTILES, GRIDY);
    discovery_hmma<<<grid, THREADS, sizeof(Smem)>>>(pos, W1, b1, b2, W3, out);
}

// round 12
// speedup vs baseline: 6.2349x; 1.0067x over previous
#include <cuda_runtime.h>
#include <cuda_fp16.h>
#include <cstdint>

#define NPTS 512
#define HDIM 128
#define TP 128
#define NPAIRS 130816
#define NTILES 1022
#define NBATCH 8
#define NB_BLK 4
#define GRIDY (NBATCH / NB_BLK)
#define THREADS 256
#define BSTRIDE 136       // fp16 per B row (272B, conflict-free ldsm)

struct Smem {
    __half bmat[HDIM * BSTRIDE];   // W2^T fp16  [d][k]
    float w1s[3 * HDIM];
    float b1s[HDIM];
    float b2s[HDIM];
    float w3s[HDIM];
    float red[NB_BLK][8];
};

__device__ __align__(16) __half g_bmat[HDIM * BSTRIDE];

// ---------------- f32x2 packed helpers ----------------
__device__ __forceinline__ uint64_t pk2(float a, float b) {
    uint64_t r; asm("mov.b64 %0, {%1,%2};" : "=l"(r) : "f"(a), "f"(b)); return r;
}
__device__ __forceinline__ void upk2(uint64_t v, float& a, float& b) {
    asm("mov.b64 {%0,%1}, %2;" : "=f"(a), "=f"(b) : "l"(v));
}
__device__ __forceinline__ uint64_t fma2(uint64_t a, uint64_t b, uint64_t c) {
    uint64_t d; asm("fma.rn.f32x2 %0, %1, %2, %3;" : "=l"(d) : "l"(a), "l"(b), "l"(c)); return d;
}
__device__ __forceinline__ uint64_t add2(uint64_t a, uint64_t b) {
    uint64_t d; asm("add.rn.f32x2 %0, %1, %2;" : "=l"(d) : "l"(a), "l"(b)); return d;
}

// pack (lo, hi) floats into f16x2
__device__ __forceinline__ uint32_t pack_f16(float lo, float hi) {
    uint32_t r;
    asm("cvt.rn.f16x2.f32 %0, %1, %2;" : "=r"(r) : "f"(hi), "f"(lo));
    return r;
}

// silu(z) = z * sigmoid(z) = 0.5z*tanh(z/2) + 0.5z ; 1 MUFU + 2 FMA per value
__device__ __forceinline__ uint32_t silu2_tanh_f16(uint64_t z2) {
    float z0, z1; upk2(z2, z0, z1);
    float h0 = 0.5f * z0, h1 = 0.5f * z1;
    float t0, t1;
    asm("tanh.approx.f32 %0, %1;" : "=f"(t0) : "f"(h0));
    asm("tanh.approx.f32 %0, %1;" : "=f"(t1) : "f"(h1));
    return pack_f16(fmaf(h0, t0, h0), fmaf(h1, t1, h1));
}

// epilogue silu (fp32 packed result), same tanh form
__device__ __forceinline__ uint64_t silu2_tanh(uint64_t z2) {
    float z0, z1; upk2(z2, z0, z1);
    float h0 = 0.5f * z0, h1 = 0.5f * z1;
    float t0, t1;
    asm("tanh.approx.f32 %0, %1;" : "=f"(t0) : "f"(h0));
    asm("tanh.approx.f32 %0, %1;" : "=f"(t1) : "f"(h1));
    return pk2(fmaf(h0, t0, h0), fmaf(h1, t1, h1));
}

__device__ __forceinline__ void ldsm_x4(uint32_t& r0, uint32_t& r1, uint32_t& r2, uint32_t& r3,
                                        uint32_t addr) {
    asm volatile("ldmatrix.sync.aligned.m8n8.x4.shared.b16 {%0,%1,%2,%3}, [%4];"
                 : "=r"(r0), "=r"(r1), "=r"(r2), "=r"(r3) : "r"(addr));
}
__device__ __forceinline__ void mma_f16(float* c, const uint32_t* a, uint32_t b0, uint32_t b1) {
    asm volatile(
        "mma.sync.aligned.m16n8k16.row.col.f32.f16.f16.f32 "
        "{%0,%1,%2,%3}, {%4,%5,%6,%7}, {%8,%9}, {%0,%1,%2,%3};"
        : "+f"(c[0]), "+f"(c[1]), "+f"(c[2]), "+f"(c[3])
        : "r"(a[0]), "r"(a[1]), "r"(a[2]), "r"(a[3]), "r"(b0), "r"(b1));
}
__device__ __forceinline__ uint32_t smem_u32(const void* p) {
    uint32_t a;
    asm("{ .reg .u64 t; cvta.to.shared.u64 t, %1; cvt.u32.u64 %0, t; }" : "=r"(a) : "l"(p));
    return a;
}

// ---------------- kernels ----------------
__global__ void init_out_kernel(float* out, const float* b3) {
    int b = threadIdx.x;
    if (b < NBATCH) out[b] = (float)NPAIRS * b3[0];
}

__global__ void prep_kernel(const float* __restrict__ W2) {
    int idx = blockIdx.x * blockDim.x + threadIdx.x;
    if (idx >= HDIM * HDIM) return;
    int d = idx & 127;
    int k = idx >> 7;
    g_bmat[d * BSTRIDE + k] = __float2half(W2[idx]);   // W2[k][d] -> B[d][k]
}

__global__ __launch_bounds__(THREADS, 2)
void discovery_hmma(const float* __restrict__ pos,
                    const float* __restrict__ W1,
                    const float* __restrict__ b1,
                    const float* __restrict__ b2,
                    const float* __restrict__ W3,
                    float* __restrict__ out) {
    extern __shared__ char smem_raw[];
    Smem* s = reinterpret_cast<Smem*>(smem_raw);

    const int t = threadIdx.x;
    const int w = t >> 5;
    const int lane = t & 31;
    const int tile = blockIdx.x;
    const int b0 = blockIdx.y * NB_BLK;

    // ---- stage weights ----
    {
        const uint4* src = (const uint4*)g_bmat;
        uint4* dst = (uint4*)s->bmat;
        for (int i = t; i < (HDIM * BSTRIDE) / 8; i += THREADS) dst[i] = src[i];
    }
    for (int i = t; i < 3 * HDIM; i += THREADS) s->w1s[i] = W1[i];
    if (t < HDIM) {
        s->b1s[t] = b1[t];
        s->b2s[t] = b2[t];
        s->w3s[t] = W3[t];
    }

    // ---- pair decode: 2 pairs per thread (rows r, r+8 of this warp's 16) ----
    int ip[2], jp[2];
    {
        const int mrow = w * 16 + (lane >> 2);
        #pragma unroll
        for (int q = 0; q < 2; ++q) {
            int p = tile * TP + mrow + q * 8;
            double tn = 2.0 * NPTS - 1.0;
            int i = (int)floor((tn - sqrt(tn * tn - 8.0 * (double)p)) * 0.5);
            if (i < 0) i = 0;
            while ((long)(i + 1) * (2 * NPTS - 1 - (i + 1)) / 2 <= p) i++;
            while ((long)i * (2 * NPTS - 1 - i) / 2 > p) i--;
            long s0 = (long)i * (2 * NPTS - 1 - i) / 2;
            ip[q] = i;
            jp[q] = i + 1 + (int)(p - s0);
        }
    }
    __syncthreads();

    const uint32_t b_base = smem_u32(s->bmat);
    const int rowoff = (lane & 7) + ((lane >> 4) << 3);
    const int kadd   = ((lane >> 3) & 1) << 3;
    const uint32_t laneB = (uint32_t)(rowoff * BSTRIDE + kadd) * 2u + b_base;
    const int kcol = (lane & 3) * 2;

    for (int bb = 0; bb < NB_BLK; ++bb) {
        const int b = b0 + bb;

        // ---- features ----
        uint64_t F0[2], F1[2], F2[2];
        {
            const float* pb = pos + (size_t)b * NPTS * 3;
            #pragma unroll
            for (int q = 0; q < 2; ++q) {
                int i = ip[q], j = jp[q];
                float dx = pb[i * 3 + 0] - pb[j * 3 + 0];
                float dy = pb[i * 3 + 1] - pb[j * 3 + 1];
                float dz = pb[i * 3 + 2] - pb[j * 3 + 2];
                float r = sqrtf(dx * dx + dy * dy + dz * dz);
                r = fmaxf(r, 0.05f);
                float ri = 1.0f / r;
                F0[q] = pk2(r, r);
                F1[q] = pk2(ri, ri);
                F2[q] = pk2(ri * ri, ri * ri);
            }
        }

        // ---- build ALL A fragments for this batch (8 k-steps x 4 regs) ----
        uint32_t afr[8][4];
        #pragma unroll
        for (int ks = 0; ks < 8; ++ks) {
            const int k0 = ks * 16 + kcol;
            float2 va0 = *(const float2*)&s->w1s[k0];
            float2 va8 = *(const float2*)&s->w1s[k0 + 8];
            float2 vb0 = *(const float2*)&s->w1s[128 + k0];
            float2 vb8 = *(const float2*)&s->w1s[128 + k0 + 8];
            float2 vc0 = *(const float2*)&s->w1s[256 + k0];
            float2 vc8 = *(const float2*)&s->w1s[256 + k0 + 8];
            float2 vd0 = *(const float2*)&s->b1s[k0];
            float2 vd8 = *(const float2*)&s->b1s[k0 + 8];
            uint64_t wa0 = pk2(va0.x, va0.y), wa8 = pk2(va8.x, va8.y);
            uint64_t wb0 = pk2(vb0.x, vb0.y), wb8 = pk2(vb8.x, vb8.y);
            uint64_t wc0 = pk2(vc0.x, vc0.y), wc8 = pk2(vc8.x, vc8.y);
            uint64_t bbv0 = pk2(vd0.x, vd0.y), bbv8 = pk2(vd8.x, vd8.y);

            uint64_t z00 = fma2(wc0, F2[0], fma2(wb0, F1[0], fma2(wa0, F0[0], bbv0)));
            uint64_t z10 = fma2(wc0, F2[1], fma2(wb0, F1[1], fma2(wa0, F0[1], bbv0)));
            uint64_t z08 = fma2(wc8, F2[0], fma2(wb8, F1[0], fma2(wa8, F0[0], bbv8)));
            uint64_t z18 = fma2(wc8, F2[1], fma2(wb8, F1[1], fma2(wa8, F0[1], bbv8)));
            afr[ks][0] = silu2_tanh_f16(z00);   // (q0; k0,k0+1)
            afr[ks][1] = silu2_tanh_f16(z10);   // (q1; k0,k0+1)
            afr[ks][2] = silu2_tanh_f16(z08);   // (q0; k0+8,k0+9)
            afr[ks][3] = silu2_tanh_f16(z18);   // (q1; k0+8,k0+9)
        }

        // ---- per column-pair: accumulate over k, then fused epilogue ----
        uint64_t sum2 = 0;
        #pragma unroll
        for (int pr = 0; pr < 8; ++pr) {
            float acc0[4] = {0.f, 0.f, 0.f, 0.f};
            float acc1[4] = {0.f, 0.f, 0.f, 0.f};
            const uint32_t prbase = laneB + (uint32_t)((pr * 16) * BSTRIDE) * 2u;
            #pragma unroll
            for (int ks = 0; ks < 8; ++ks) {
                uint32_t h0, h1v, h2v, h3v;
                ldsm_x4(h0, h1v, h2v, h3v, prbase + (uint32_t)(ks * 16) * 2u);
                mma_f16(acc0, afr[ks], h0,  h1v);
                mma_f16(acc1, afr[ks], h2v, h3v);
            }
            // epilogue for cols pr*16 + kcol (+0/+8)
            {
                int col = pr * 16 + kcol;
                float2 b2a = *(const float2*)&s->b2s[col];
                float2 w3a = *(const float2*)&s->w3s[col];
                float2 b2b = *(const float2*)&s->b2s[col + 8];
                float2 w3b = *(const float2*)&s->w3s[col + 8];
                uint64_t b2va = pk2(b2a.x, b2a.y), w3va = pk2(w3a.x, w3a.y);
                uint64_t b2vb = pk2(b2b.x, b2b.y), w3vb = pk2(w3b.x, w3b.y);
                uint64_t za0 = add2(pk2(acc0[0], acc0[1]), b2va);
                uint64_t za1 = add2(pk2(acc0[2], acc0[3]), b2va);
                uint64_t zb0 = add2(pk2(acc1[0], acc1[1]), b2vb);
                uint64_t zb1 = add2(pk2(acc1[2], acc1[3]), b2vb);
                sum2 = fma2(silu2_tanh(za0), w3va, sum2);
                sum2 = fma2(silu2_tanh(za1), w3va, sum2);
                sum2 = fma2(silu2_tanh(zb0), w3vb, sum2);
                sum2 = fma2(silu2_tanh(zb1), w3vb, sum2);
            }
        }
        float sa, sb;
        upk2(sum2, sa, sb);
        float sum = sa + sb;

        #pragma unroll
        for (int off = 16; off > 0; off >>= 1)
            sum += __shfl_xor_sync(0xFFFFFFFFu, sum, off);
        if (lane == 0) s->red[bb][w] = sum;
    }

    __syncthreads();
    if (w == 0 && lane < NB_BLK) {
        float tot = 0.0f;
        #pragma unroll
        for (int wi = 0; wi < 8; ++wi) tot += s->red[lane][wi];
        atomicAdd(&out[b0 + lane], tot);
    }
}

extern "C" void kernel_launch(void* const* d_in, const int* in_sizes, int n_in,
                              void* d_out, int out_size) {
    const float* pos = (const float*)d_in[0];
    const float* W1  = (const float*)d_in[1];
    const float* b1  = (const float*)d_in[2];
    const float* W2  = (const float*)d_in[3];
    const float* b2  = (const float*)d_in[4];
    const float* W3  = (const float*)d_in[5];
    const float* b3  = (const float*)d_in[6];
    float* out = (float*)d_out;

    cudaFuncSetAttribute(discovery_hmma,
                         cudaFuncAttributeMaxDynamicSharedMemorySize, (int)sizeof(Smem));

    init_out_kernel<<<1, NBATCH>>>(out, b3);
    prep_kernel<<<64, 256>>>(W2);
    dim3 grid(NTILES, GRIDY);
    discovery_hmma<<<grid, THREADS, sizeof(Smem)>>>(pos, W1, b1, b2, W3, out);
}